// round 8
// baseline (speedup 1.0000x reference)
#include <cuda_runtime.h>

// PCNN recurrence B=32, T=64, L=8192 — time-chunked warp-autonomous trapezoids,
// packed f32x2 math + MUFU tanh sigmoid.
//
// Same decomposition as R4 (SEG=1024, region 1184, TC=16, NW=12), but the
// per-element math runs on the dual-fp32 pipe (fma.rn.f32x2) with state held
// as 4 packed pairs, and sigmoid(z) = 0.5 + 0.5*tanh(z/2) with z/2 obtained
// free by tracking u/2 and -e/2.

#define Tn   64
#define Ln   8192
#define Bn   32
#define SEG  1024
#define TC   16
#define NW   12
#define WR   (96 * NW + 32)     // 1184 region cells
#define NTH  (NW * 32)          // 384

typedef unsigned long long u64;

__device__ __forceinline__ u64 pk(float lo, float hi) {
    u64 r; asm("mov.b64 %0,{%1,%2};" : "=l"(r) : "f"(lo), "f"(hi)); return r;
}
__device__ __forceinline__ void upk(u64 v, float& lo, float& hi) {
    asm("mov.b64 {%0,%1},%2;" : "=f"(lo), "=f"(hi) : "l"(v));
}
__device__ __forceinline__ u64 fma2(u64 a, u64 b, u64 c) {
    u64 d; asm("fma.rn.f32x2 %0,%1,%2,%3;" : "=l"(d) : "l"(a), "l"(b), "l"(c)); return d;
}
__device__ __forceinline__ u64 add2(u64 a, u64 b) {
    u64 d; asm("add.rn.f32x2 %0,%1,%2;" : "=l"(d) : "l"(a), "l"(b)); return d;
}
__device__ __forceinline__ u64 mul2(u64 a, u64 b) {
    u64 d; asm("mul.rn.f32x2 %0,%1,%2;" : "=l"(d) : "l"(a), "l"(b)); return d;
}
__device__ __forceinline__ float tanhap(float z) {
    float r; asm("tanh.approx.f32 %0,%1;" : "=f"(r) : "f"(z)); return r;
}

__global__ __launch_bounds__(NTH, 2)
void pcnn_kernel(const float* __restrict__ x,
                 const float* __restrict__ w,
                 float* __restrict__ out)
{
    const int tid  = threadIdx.x;
    const int warp = tid >> 5;
    const int lane = tid & 31;
    const int b    = blockIdx.y;
    const int s0   = blockIdx.x * SEG;
    const int off  = 96 * warp + 4 * lane;   // region-rel base of 4 elems
    const int q0   = s0 - 80 + off;          // absolute position of elem 0

    const float w0s = __ldg(&w[0]);
    const float w1s = __ldg(&w[1]);
    const float w2s = __ldg(&w[2]);

    const u64 W0 = pk(w0s, w0s), W1 = pk(w1s, w1s), W2 = pk(w2s, w2s);
    const u64 DF = pk(0.90483741803595952f, 0.90483741803595952f);  // exp(-0.1)
    const u64 DL = pk(0.36787944117144233f, 0.36787944117144233f);  // exp(-1)
    const u64 DE = DL;
    const u64 Q  = pk(0.25f, 0.25f);
    const u64 H  = pk(0.5f, 0.5f);
    const u64 NVH = pk(-5.0f, -5.0f);        // -(V_E)/2

    const bool inL  = (q0 >= 0) && (q0 < Ln);
    const bool own  = (lane >= 4) && (lane < 28);
    const bool pOut = own && (q0 >= s0) && (q0 < s0 + SEG);

    // clamped x address (always safe to load; garbage only feeds !inL lanes)
    int qc = q0 < 0 ? 0 : (q0 > Ln - 4 ? Ln - 4 : q0);
    const ulonglong2* xrow = (const ulonglong2*)(x + (size_t)(b * Tn) * Ln) + (qc >> 2);
    ulonglong2*       op   = (ulonglong2*)(out + (size_t)(b * Tn) * Ln) + (q0 >> 2);

    __shared__ float ys[WR];
    if (tid < WR / 4) ((float4*)ys)[tid] = make_float4(0.f, 0.f, 0.f, 0.f);

    u64 F01 = 0, F23 = 0, L01 = 0, L23 = 0;
    u64 E01 = pk(-5.f, -5.f), E23 = pk(-5.f, -5.f);   // En = -e/2, e0 = V_E/ALPHA_E = 10
    u64 Y01 = 0, Y23 = 0;

    ulonglong2 xv = __ldg(xrow);   // x at t=0
    __syncthreads();               // smem init visible

    int t = 0;
#pragma unroll 1
    for (int c = 0; c < Tn / TC; ++c) {
        // chunk start: reload full 128-wide warp region from smem
        {
            ulonglong2 yv = *(const ulonglong2*)&ys[off];
            Y01 = yv.x; Y23 = yv.y;
        }
        __syncthreads();

#pragma unroll
        for (int s = 0; s < TC; ++s) {
            // prefetch x for next step (clamped at t=63; value unused then)
            const int tn = (t + 1 < Tn) ? (t + 1) : (Tn - 1);
            const ulonglong2 xn = __ldg(xrow + (size_t)tn * (Ln / 4));

            float y0, y1, y2, y3;
            upk(Y01, y0, y1); upk(Y23, y2, y3);
            const float yl = __shfl_up_sync(0xffffffffu, y3, 1);   // lane0 garbage: cone-safe
            const float yr = __shfl_down_sync(0xffffffffu, y0, 1); // lane31 garbage: cone-safe

            const u64 A = pk(yl, y0);
            const u64 B = pk(y1, y2);       // shared: yp of pair01, ym of pair23
            const u64 C = pk(y3, yr);

            // f = df*f + x + (w0*ym + w1*y + w2*yp)
            const u64 cv0 = fma2(W0, A, fma2(W1, Y01, mul2(W2, B)));
            const u64 cv1 = fma2(W0, B, fma2(W1, Y23, mul2(W2, C)));
            F01 = add2(fma2(DF, F01, xv.x), cv0);
            F23 = add2(fma2(DF, F23, xv.y), cv1);

            // l = dl*l + ym + yp
            L01 = fma2(DL, L01, add2(A, B));
            L23 = fma2(DL, L23, add2(B, C));

            // u/2 = f * (0.25*l + 0.5)
            const u64 U0 = mul2(F01, fma2(Q, L01, H));
            const u64 U1 = mul2(F23, fma2(Q, L23, H));

            // En = de*En - 5*y   (En = -e/2)
            E01 = fma2(DE, E01, mul2(NVH, Y01));
            E23 = fma2(DE, E23, mul2(NVH, Y23));

            // z/2 = u/2 + En ;  y = 0.5 + 0.5*tanh(z/2)
            float z0, z1, z2, z3;
            upk(add2(U0, E01), z0, z1);
            upk(add2(U1, E23), z2, z3);
            Y01 = fma2(H, pk(tanhap(z0), tanhap(z1)), H);
            Y23 = fma2(H, pk(tanhap(z2), tanhap(z3)), H);

            // positions outside [0,L) emulate the zero pad
            if (!inL) { Y01 = 0; Y23 = 0; }

            if (pOut) { ulonglong2 o; o.x = Y01; o.y = Y23; *op = o; }
            op += (Ln / 4);

            xv = xn;
            ++t;
        }

        // chunk end: publish owned 96 (lanes 4..27)
        if (own) { ulonglong2 o; o.x = Y01; o.y = Y23; *(ulonglong2*)&ys[off] = o; }
        __syncthreads();
    }
}

extern "C" void kernel_launch(void* const* d_in, const int* in_sizes, int n_in,
                              void* d_out, int out_size)
{
    const float* x = (const float*)d_in[0];   // [32, 64, 8192] f32
    const float* w = (const float*)d_in[1];   // [3] f32
    float* out = (float*)d_out;               // [32, 64, 8192] f32

    dim3 grid(Ln / SEG, Bn);   // (8, 32) = 256 blocks of 384 threads
    pcnn_kernel<<<grid, NTH>>>(x, w, out);
}

// round 14
// speedup vs baseline: 1.0651x; 1.0651x over previous
#include <cuda_runtime.h>

// PCNN recurrence B=32, T=64, L=8192 — time-chunked warp-autonomous trapezoids,
// packed f32x2 math + MUFU tanh sigmoid + 3-deep register x-prefetch pipeline.
//
// Decomposition (proven in R4/R8): block owns SEG=1024 of one batch row and
// computes region 1184 (halo 80/side = 64 + 16 chunk slack); T split into 4
// chunks of TC=16. Each warp holds 128 y elems in registers (4/thread),
// exchanges lane-edge neighbors with 2 shuffles/step; cone shrinks 1/step so
// its central 96 stay exact. y re-exchanged through SMEM at chunk ends only.
// x rows t..t+2 are held in 3 in-flight register buffers (row t+3 issued at
// step t), covering the ~500cyc DRAM latency that bounded R8.

#define Tn   64
#define Ln   8192
#define Bn   32
#define SEG  1024
#define TC   16
#define NW   12
#define WR   (96 * NW + 32)     // 1184 region cells
#define NTH  (NW * 32)          // 384

typedef unsigned long long u64;

__device__ __forceinline__ u64 pk(float lo, float hi) {
    u64 r; asm("mov.b64 %0,{%1,%2};" : "=l"(r) : "f"(lo), "f"(hi)); return r;
}
__device__ __forceinline__ void upk(u64 v, float& lo, float& hi) {
    asm("mov.b64 {%0,%1},%2;" : "=f"(lo), "=f"(hi) : "l"(v));
}
__device__ __forceinline__ u64 fma2(u64 a, u64 b, u64 c) {
    u64 d; asm("fma.rn.f32x2 %0,%1,%2,%3;" : "=l"(d) : "l"(a), "l"(b), "l"(c)); return d;
}
__device__ __forceinline__ u64 add2(u64 a, u64 b) {
    u64 d; asm("add.rn.f32x2 %0,%1,%2;" : "=l"(d) : "l"(a), "l"(b)); return d;
}
__device__ __forceinline__ u64 mul2(u64 a, u64 b) {
    u64 d; asm("mul.rn.f32x2 %0,%1,%2;" : "=l"(d) : "l"(a), "l"(b)); return d;
}
__device__ __forceinline__ float tanhap(float z) {
    float r; asm("tanh.approx.f32 %0,%1;" : "=f"(r) : "f"(z)); return r;
}

__global__ __launch_bounds__(NTH, 2)
void pcnn_kernel(const float* __restrict__ x,
                 const float* __restrict__ w,
                 float* __restrict__ out)
{
    const int tid  = threadIdx.x;
    const int warp = tid >> 5;
    const int lane = tid & 31;
    const int b    = blockIdx.y;
    const int s0   = blockIdx.x * SEG;
    const int off  = 96 * warp + 4 * lane;   // region-rel base of 4 elems
    const int q0   = s0 - 80 + off;          // absolute position of elem 0

    const float w0s = __ldg(&w[0]);
    const float w1s = __ldg(&w[1]);
    const float w2s = __ldg(&w[2]);

    const u64 W0 = pk(w0s, w0s), W1 = pk(w1s, w1s), W2 = pk(w2s, w2s);
    const u64 DF = pk(0.90483741803595952f, 0.90483741803595952f);  // exp(-0.1)
    const u64 DL = pk(0.36787944117144233f, 0.36787944117144233f);  // exp(-1)
    const u64 Q  = pk(0.25f, 0.25f);
    const u64 H  = pk(0.5f, 0.5f);
    const u64 NVH = pk(-5.0f, -5.0f);        // -(V_E)/2

    const bool inL  = (q0 >= 0) && (q0 < Ln);
    const bool own  = (lane >= 4) && (lane < 28);
    const bool pOut = own && (q0 >= s0) && (q0 < s0 + SEG);

    // clamped x address (always safe to load; garbage only feeds !inL lanes)
    const int qc = q0 < 0 ? 0 : (q0 > Ln - 4 ? Ln - 4 : q0);
    const ulonglong2* xrow = (const ulonglong2*)(x + (size_t)(b * Tn) * Ln) + (qc >> 2);
    float4*           op   = (float4*)(out + (size_t)(b * Tn) * Ln) + (q0 >> 2);

    __shared__ float ys[WR];
    if (tid < WR / 4) ((float4*)ys)[tid] = make_float4(0.f, 0.f, 0.f, 0.f);

    u64 F01 = 0, F23 = 0, L01 = 0, L23 = 0;
    u64 E01 = pk(-5.f, -5.f), E23 = pk(-5.f, -5.f);   // En = -e/2, e0 = 10
    u64 Y01 = 0, Y23 = 0;

    // x pipeline: rows t, t+1, t+2 in flight (issue distance 3)
    ulonglong2 xv  = __ldg(xrow);                         // row 0
    ulonglong2 xn1 = __ldg(xrow + (size_t)1 * (Ln / 4));  // row 1
    ulonglong2 xn2 = __ldg(xrow + (size_t)2 * (Ln / 4));  // row 2

    __syncthreads();   // ys init visible

    int t = 0;
#pragma unroll 1
    for (int c = 0; c < Tn / TC; ++c) {
        // chunk start: reload full 128-wide warp region from smem
        {
            ulonglong2 yv = *(const ulonglong2*)&ys[off];
            Y01 = yv.x; Y23 = yv.y;
        }
        __syncthreads();

#pragma unroll
        for (int s = 0; s < TC; ++s) {
            // rotate pipeline; issue row t+3 (clamped; value past t=63 unused)
            const ulonglong2 xc = xv;      // row t (consumed this step)
            xv = xn1; xn1 = xn2;
            const int tn = min(t + 3, Tn - 1);
            xn2 = __ldg(xrow + (size_t)tn * (Ln / 4));

            float y0, y1, y2, y3;
            upk(Y01, y0, y1); upk(Y23, y2, y3);
            const float yl = __shfl_up_sync(0xffffffffu, y3, 1);   // lane0 garbage: cone-safe
            const float yr = __shfl_down_sync(0xffffffffu, y0, 1); // lane31 garbage: cone-safe

            const u64 A = pk(yl, y0);
            const u64 B = pk(y1, y2);       // shared: yp of pair01, ym of pair23
            const u64 C = pk(y3, yr);

            // f = df*f + x + (w0*ym + w1*y + w2*yp)
            const u64 cv0 = fma2(W0, A, fma2(W1, Y01, mul2(W2, B)));
            const u64 cv1 = fma2(W0, B, fma2(W1, Y23, mul2(W2, C)));
            F01 = add2(fma2(DF, F01, xc.x), cv0);
            F23 = add2(fma2(DF, F23, xc.y), cv1);

            // l = dl*l + ym + yp
            L01 = fma2(DL, L01, add2(A, B));
            L23 = fma2(DL, L23, add2(B, C));

            // u/2 = f * (0.25*l + 0.5)
            const u64 U0 = mul2(F01, fma2(Q, L01, H));
            const u64 U1 = mul2(F23, fma2(Q, L23, H));

            // En = de*En - 5*y   (En = -e/2)
            E01 = fma2(DL, E01, mul2(NVH, Y01));
            E23 = fma2(DL, E23, mul2(NVH, Y23));

            // z/2 = u/2 + En ;  y = 0.5 + 0.5*tanh(z/2)
            float z0, z1, z2, z3;
            upk(add2(U0, E01), z0, z1);
            upk(add2(U1, E23), z2, z3);
            Y01 = fma2(H, pk(tanhap(z0), tanhap(z1)), H);
            Y23 = fma2(H, pk(tanhap(z2), tanhap(z3)), H);

            // positions outside [0,L) emulate the zero pad
            if (!inL) { Y01 = 0; Y23 = 0; }

            if (pOut) {
                float o0, o1, o2, o3;
                upk(Y01, o0, o1); upk(Y23, o2, o3);
                __stcs(op, make_float4(o0, o1, o2, o3));   // streaming: don't pollute L2
            }
            op += (Ln / 4);

            ++t;
        }

        // chunk end: publish owned 96 (lanes 4..27)
        if (own) { ulonglong2 o; o.x = Y01; o.y = Y23; *(ulonglong2*)&ys[off] = o; }
        __syncthreads();
    }
}

extern "C" void kernel_launch(void* const* d_in, const int* in_sizes, int n_in,
                              void* d_out, int out_size)
{
    const float* x = (const float*)d_in[0];   // [32, 64, 8192] f32
    const float* w = (const float*)d_in[1];   // [3] f32
    float* out = (float*)d_out;               // [32, 64, 8192] f32

    dim3 grid(Ln / SEG, Bn);   // (8, 32) = 256 blocks of 384 threads
    pcnn_kernel<<<grid, NTH>>>(x, w, out);
}